// round 9
// baseline (speedup 1.0000x reference)
#include <cuda_runtime.h>
#include <cuda_fp16.h>
#include <math.h>
#include <stdint.h>

#define D_MODEL 2048
#define D_FF    8192
#define BATCH   4
#define SEQ     2048
#define NTOK    (BATCH * SEQ)

// ---------------------------------------------------------------------------
// Scratch
// ---------------------------------------------------------------------------
__device__ float  g_xln [(size_t)NTOK * D_MODEL];        // LN1 out fp32 (residual)
__device__ float  g_sc  [(size_t)BATCH * SEQ * SEQ];     // scores fp32
__device__ float  g_src2[(size_t)NTOK * D_MODEL];        // post-attn residual fp32
__device__ __half g_qkv_h[(size_t)NTOK * 3 * D_MODEL];   // QKV half
__device__ __half g_xln_h[(size_t)NTOK * D_MODEL];
__device__ __half g_q_h [(size_t)NTOK * D_MODEL];
__device__ __half g_k_h [(size_t)NTOK * D_MODEL];
__device__ __half g_vt_h[(size_t)NTOK * D_MODEL];        // V^T [B, d, S]
__device__ __half g_p_h [(size_t)BATCH * SEQ * SEQ];     // probs half
__device__ __half g_at_h[(size_t)NTOK * D_MODEL];        // attn half
__device__ __half g_hln_h[(size_t)NTOK * D_MODEL];
__device__ __half g_h1_h[(size_t)NTOK * D_FF];
__device__ __half g_wqkv[(size_t)3 * D_MODEL * D_MODEL];
__device__ __half g_wo  [(size_t)D_MODEL * D_MODEL];
__device__ __half g_w1  [(size_t)D_FF * D_MODEL];
__device__ __half g_w2  [(size_t)D_MODEL * D_FF];

__device__ __forceinline__ uint32_t smem_u32(const void* p) {
    uint32_t a;
    asm("{ .reg .u64 t; cvta.to.shared.u64 t, %1; cvt.u32.u64 %0, t; }" : "=r"(a) : "l"(p));
    return a;
}

#define MMA_F16(d, a, b)                                                       \
    asm volatile("mma.sync.aligned.m16n8k16.row.col.f32.f16.f16.f32 "          \
        "{%0,%1,%2,%3}, {%4,%5,%6,%7}, {%8,%9}, {%0,%1,%2,%3};"                \
        : "+f"((d)[0]), "+f"((d)[1]), "+f"((d)[2]), "+f"((d)[3])               \
        : "r"((a)[0]), "r"((a)[1]), "r"((a)[2]), "r"((a)[3]),                  \
          "r"((b)[0]), "r"((b)[1]))

#define LDM4(r0, r1, r2, r3, ad)                                               \
    asm volatile("ldmatrix.sync.aligned.m8n8.x4.shared.b16 {%0,%1,%2,%3}, [%4];" \
        : "=r"(r0), "=r"(r1), "=r"(r2), "=r"(r3) : "r"(ad))

#define CP16(dst, src) \
    asm volatile("cp.async.cg.shared.global [%0], [%1], 16;" :: "r"(dst), "l"(src))
#define CP_COMMIT() asm volatile("cp.async.commit_group;" ::: "memory")
#define CP_WAIT(n)  asm volatile("cp.async.wait_group %0;" :: "n"(n) : "memory")

// ---------------------------------------------------------------------------
// fp16 mma GEMM: C[M,N] = scale*(A @ B^T) [+bias][+res][relu]
// A:[M,K] half row-major, B:[N,K] half row-major. M mult 256, N mult 128,
// K mult 64. CTA 256x128x64, 8 warps (4m x 2n), warp 64x64, ldmatrix.x4.
// 3-stage cp.async, 1 CTA/SM. Row pitch 144 B (conflict-free verified).
// ---------------------------------------------------------------------------
#define BM        256
#define BN        128
#define BK        64
#define PITCH_B   144
#define ATILE_B   (BM * PITCH_B)         // 36864
#define BTILE_B   (BN * PITCH_B)         // 18432
#define STAGE_B   (ATILE_B + BTILE_B)    // 55296
#define STAGES    3
#define SMEM_BYTES (STAGES * STAGE_B)    // 165888
#define NTHREADS  256

__global__ __launch_bounds__(NTHREADS)
void hgemm_k(const __half* __restrict__ A, int lda, long long sA,
             const __half* __restrict__ B, int ldb, long long sB,
             void*         __restrict__ Cv, int ldc, long long sC,
             int K,
             const float* __restrict__ bias,
             const float* __restrict__ res,
             float scale, int relu, int causal_skip, int klimit, int half_out)
{
    const int bm = blockIdx.y * BM;
    const int bn = blockIdx.x * BN;
    if (causal_skip && bn > bm + (BM - BN)) return;   // bn > bm+128: fully above diag

    extern __shared__ float sm[];
    const uint32_t sbase = smem_u32(sm);

    const int tid = threadIdx.x;
    const int wid = tid >> 5;
    const int lane = tid & 31;
    const int g   = lane >> 2;
    const int tig = lane & 3;
    const int wm  = wid >> 1;            // 0..3
    const int wn  = wid & 1;             // 0..1
    const uint32_t lrow = (lane & 7) + ((lane >> 3) & 1) * 8;
    const uint32_t lk16 = (lane >> 4) * 16;

    const long long bz = blockIdx.z;
    A += bz * sA;  B += bz * sB;
    const float* R = res ? res + bz * sC : nullptr;

    int Keff = K;
    if (klimit) { int kl = bm + BM; Keff = (kl < K) ? kl : K; }
    const int KT = Keff / BK;

    const __half* Abase = A + (long long)bm * lda;
    const __half* Bbase = B + (long long)bn * ldb;

#define ISSUE(kt_, st_) do {                                                   \
    const int _k0 = (kt_) * BK;                                                \
    const uint32_t _so = (uint32_t)(st_) * STAGE_B;                            \
    _Pragma("unroll")                                                          \
    for (int t = 0; t < 8; t++) {                                              \
        int c = tid + t * NTHREADS;                                            \
        int row = c >> 3, chk = c & 7;                                         \
        CP16(sbase + _so + (uint32_t)row * PITCH_B + (uint32_t)(chk << 4),     \
             Abase + (long long)row * lda + _k0 + (chk << 3));                 \
    }                                                                          \
    _Pragma("unroll")                                                          \
    for (int t = 0; t < 4; t++) {                                              \
        int c = tid + t * NTHREADS;                                            \
        int row = c >> 3, chk = c & 7;                                         \
        CP16(sbase + _so + ATILE_B + (uint32_t)row * PITCH_B + (uint32_t)(chk << 4), \
             Bbase + (long long)row * ldb + _k0 + (chk << 3));                 \
    }                                                                          \
} while (0)

    float acc[4][8][4];
#pragma unroll
    for (int i = 0; i < 4; i++)
#pragma unroll
        for (int j = 0; j < 8; j++)
#pragma unroll
            for (int r = 0; r < 4; r++) acc[i][j][r] = 0.f;

#pragma unroll
    for (int s = 0; s < STAGES - 1; s++) { ISSUE(s, s); CP_COMMIT(); }
    CP_WAIT(STAGES - 2);
    __syncthreads();

    const uint32_t aAddr0 = sbase + (wm * 64 + lrow) * PITCH_B + lk16;
    const uint32_t bAddr0 = sbase + ATILE_B + (wn * 64 + lrow) * PITCH_B + lk16;

    for (int kt = 0; kt < KT; kt++) {
        const int next = kt + STAGES - 1;
        if (next < KT) ISSUE(next, next % STAGES);
        CP_COMMIT();

        const uint32_t so = (uint32_t)(kt % STAGES) * STAGE_B;

#pragma unroll
        for (int ks = 0; ks < 4; ks++) {
            uint32_t a[4][4], b[8][2];
#pragma unroll
            for (int mf = 0; mf < 4; mf++)
                LDM4(a[mf][0], a[mf][1], a[mf][2], a[mf][3],
                     aAddr0 + so + (uint32_t)(mf * 16) * PITCH_B + ks * 32);
#pragma unroll
            for (int np = 0; np < 4; np++)
                LDM4(b[2 * np][0], b[2 * np + 1][0], b[2 * np][1], b[2 * np + 1][1],
                     bAddr0 + so + (uint32_t)(np * 16) * PITCH_B + ks * 32);
#pragma unroll
            for (int mf = 0; mf < 4; mf++)
#pragma unroll
                for (int nf = 0; nf < 8; nf++)
                    MMA_F16(acc[mf][nf], a[mf], b[nf]);
        }
        CP_WAIT(STAGES - 2);
        __syncthreads();
    }

    // epilogue: c0=(g,2tig) c1=(g,2tig+1) c2=(g+8,2tig) c3=(g+8,2tig+1)
    float*  Cf = (float*)Cv  + bz * sC;
    __half* Ch = (__half*)Cv + bz * sC;
#pragma unroll
    for (int mf = 0; mf < 4; mf++) {
        const int m0 = bm + wm * 64 + mf * 16 + g;
#pragma unroll
        for (int nf = 0; nf < 8; nf++) {
            const int n0 = bn + wn * 64 + nf * 8 + 2 * tig;
            float2 v0, v1;
            v0.x = acc[mf][nf][0] * scale; v0.y = acc[mf][nf][1] * scale;
            v1.x = acc[mf][nf][2] * scale; v1.y = acc[mf][nf][3] * scale;
            if (bias) {
                float bx = __ldg(bias + n0), by = __ldg(bias + n0 + 1);
                v0.x += bx; v0.y += by; v1.x += bx; v1.y += by;
            }
            if (R) {
                float2 r0 = *(const float2*)(R + (long long)m0 * ldc + n0);
                float2 r1 = *(const float2*)(R + (long long)(m0 + 8) * ldc + n0);
                v0.x += r0.x; v0.y += r0.y; v1.x += r1.x; v1.y += r1.y;
            }
            if (relu) {
                v0.x = fmaxf(v0.x, 0.f); v0.y = fmaxf(v0.y, 0.f);
                v1.x = fmaxf(v1.x, 0.f); v1.y = fmaxf(v1.y, 0.f);
            }
            if (half_out) {
                *(__half2*)(Ch + (long long)m0 * ldc + n0)       = __floats2half2_rn(v0.x, v0.y);
                *(__half2*)(Ch + (long long)(m0 + 8) * ldc + n0) = __floats2half2_rn(v1.x, v1.y);
            } else {
                *(float2*)(Cf + (long long)m0 * ldc + n0)       = v0;
                *(float2*)(Cf + (long long)(m0 + 8) * ldc + n0) = v1;
            }
        }
    }
}

// ---------------------------------------------------------------------------
// fp32 -> fp16 conversion (weights)
// ---------------------------------------------------------------------------
__global__ __launch_bounds__(256)
void cvt_k(const float* __restrict__ x, __half* __restrict__ y, long long n4)
{
    long long i = (long long)blockIdx.x * 256 + threadIdx.x;
    if (i < n4) {
        float4 v = ((const float4*)x)[i];
        __half2 h0 = __floats2half2_rn(v.x, v.y);
        __half2 h1 = __floats2half2_rn(v.z, v.w);
        ((uint2*)y)[i] = make_uint2(*(uint32_t*)&h0, *(uint32_t*)&h1);
    }
}

// ---------------------------------------------------------------------------
// LayerNorm: optional fp32 out (residual) + half out (GEMM input)
// ---------------------------------------------------------------------------
__global__ __launch_bounds__(256)
void ln_k(const float* __restrict__ x, const float* __restrict__ g,
          const float* __restrict__ b, float* __restrict__ y, __half* __restrict__ yh)
{
    const int D = D_MODEL;
    const long long row = blockIdx.x;
    const float* xr = x + row * D;
    __half*      hr = yh + row * D;
    const int tid = threadIdx.x;

    __shared__ float sh[256];
    float v[8];
    float s = 0.f;
#pragma unroll
    for (int i = 0; i < 8; i++) { v[i] = xr[tid + i * 256]; s += v[i]; }
    sh[tid] = s; __syncthreads();
    for (int o = 128; o > 0; o >>= 1) { if (tid < o) sh[tid] += sh[tid + o]; __syncthreads(); }
    const float mean = sh[0] * (1.f / D);
    __syncthreads();

    s = 0.f;
#pragma unroll
    for (int i = 0; i < 8; i++) { float d = v[i] - mean; s += d * d; }
    sh[tid] = s; __syncthreads();
    for (int o = 128; o > 0; o >>= 1) { if (tid < o) sh[tid] += sh[tid + o]; __syncthreads(); }
    const float r = rsqrtf(sh[0] * (1.f / D) + 1e-5f);

    float* yr = y ? y + row * D : nullptr;
#pragma unroll
    for (int i = 0; i < 8; i++) {
        int j = tid + i * 256;
        float o = (v[i] - mean) * r * __ldg(g + j) + __ldg(b + j);
        if (yr) yr[j] = o;
        hr[j] = __float2half_rn(o);
    }
}

// ---------------------------------------------------------------------------
// RoPE (reference-exact trig-of-trig), half in / half out
// ---------------------------------------------------------------------------
__global__ __launch_bounds__(256)
void rope_k(const __half* __restrict__ qkv, __half* __restrict__ Qo, __half* __restrict__ Ko)
{
    const int d = D_MODEL, half = D_MODEL / 2;
    const int t = blockIdx.x, b = blockIdx.y;
    const long long rq = ((long long)b * SEQ + t) * (3 * D_MODEL);
    const __half* Q = qkv + rq;
    const __half* K = qkv + rq + d;
    const long long ro = ((long long)b * SEQ + t) * d;
    const float pos = (float)t;
    const float l2c = -13.28771238f / 1024.f;   // -log2(10000)/1024

#pragma unroll
    for (int i = 0; i < 8; i++) {
        int j = threadIdx.x + i * 256;
        int fidx = (j < half) ? j : (j - half);
        float invf = exp2f(l2c * (float)fidx);
        float sp = pos * invf;
        float e = (j < half) ? sinf(sp) : cosf(sp);
        float c = cosf(e), s = sinf(e);
        float rqv, rkv;
        if (j < half) { rqv = -__half2float(Q[2 * j]);
                        rkv = -__half2float(K[2 * j]); }
        else          { rqv =  __half2float(Q[2 * (j - half) + 1]);
                        rkv =  __half2float(K[2 * (j - half) + 1]); }
        Qo[ro + j] = __float2half_rn(__half2float(Q[j]) * c + rqv * s);
        Ko[ro + j] = __float2half_rn(__half2float(K[j]) * c - rkv * s);
    }
}

// ---------------------------------------------------------------------------
// V transpose (half in/out): vt[b, n, s] = qkv[b, s, 2d + n]
// ---------------------------------------------------------------------------
__global__ __launch_bounds__(256)
void vtrans_k(const __half* __restrict__ qkv, __half* __restrict__ vt)
{
    __shared__ __half t[32][33];
    const int b = blockIdx.z;
    const int s0 = blockIdx.y * 32, n0 = blockIdx.x * 32;
    const int x = threadIdx.x, y = threadIdx.y;
#pragma unroll
    for (int i = 0; i < 32; i += 8)
        t[y + i][x] = qkv[((long long)b * SEQ + s0 + y + i) * (3 * D_MODEL) + 2 * D_MODEL + n0 + x];
    __syncthreads();
#pragma unroll
    for (int i = 0; i < 32; i += 8)
        vt[((long long)b * D_MODEL + n0 + y + i) * SEQ + s0 + x] = t[x][y + i];
}

// ---------------------------------------------------------------------------
// Causal softmax: fp32 scores in, half probs out (cols < ceil128(q+1))
// ---------------------------------------------------------------------------
__global__ __launch_bounds__(256)
void softmax_k(const float* __restrict__ S_, __half* __restrict__ P)
{
    const int S = SEQ;
    const int q = blockIdx.x, b = blockIdx.y;
    const float* row = S_ + ((long long)b * S + q) * S;
    __half* prow = P + ((long long)b * S + q) * S;
    const int n = q + 1;
    const int klim = ((q >> 7) + 1) << 7;
    const int tid = threadIdx.x;
    __shared__ float sh[256];

    float v[8];
    float mx = -3.402823e38f;
#pragma unroll
    for (int i = 0; i < 8; i++) {
        int j = tid + i * 256;
        v[i] = (j < n) ? row[j] : -3.402823e38f;
        mx = fmaxf(mx, v[i]);
    }
    sh[tid] = mx; __syncthreads();
    for (int o = 128; o > 0; o >>= 1) { if (tid < o) sh[tid] = fmaxf(sh[tid], sh[tid + o]); __syncthreads(); }
    mx = sh[0]; __syncthreads();

    float sum = 0.f;
#pragma unroll
    for (int i = 0; i < 8; i++) {
        int j = tid + i * 256;
        v[i] = (j < n) ? expf(v[i] - mx) : 0.f;
        sum += v[i];
    }
    sh[tid] = sum; __syncthreads();
    for (int o = 128; o > 0; o >>= 1) { if (tid < o) sh[tid] += sh[tid + o]; __syncthreads(); }
    const float inv = 1.f / sh[0];

#pragma unroll
    for (int i = 0; i < 8; i++) {
        int j = tid + i * 256;
        if (j < klim) prow[j] = __float2half_rn(v[i] * inv);
    }
}

// ---------------------------------------------------------------------------
// Launch
// ---------------------------------------------------------------------------
extern "C" void kernel_launch(void* const* d_in, const int* in_sizes, int n_in,
                              void* d_out, int out_size)
{
    const float* src  = (const float*)d_in[0];
    const float* Wqkv = (const float*)d_in[1];
    const float* bqkv = (const float*)d_in[2];
    const float* Wo   = (const float*)d_in[3];
    const float* bo   = (const float*)d_in[4];
    const float* W1   = (const float*)d_in[5];
    const float* b1   = (const float*)d_in[6];
    const float* W2   = (const float*)d_in[7];
    const float* b2   = (const float*)d_in[8];
    const float* g1   = (const float*)d_in[9];
    const float* be1  = (const float*)d_in[10];
    const float* g2   = (const float*)d_in[11];
    const float* be2  = (const float*)d_in[12];
    float* out = (float*)d_out;

    float *xln, *sc, *src2;
    __half *qkv_h, *xln_h, *q_h, *k_h, *vt_h, *p_h, *at_h, *hln_h, *h1_h;
    __half *wqkv, *wo, *w1, *w2;
    cudaGetSymbolAddress((void**)&xln,   g_xln);
    cudaGetSymbolAddress((void**)&sc,    g_sc);
    cudaGetSymbolAddress((void**)&src2,  g_src2);
    cudaGetSymbolAddress((void**)&qkv_h, g_qkv_h);
    cudaGetSymbolAddress((void**)&xln_h, g_xln_h);
    cudaGetSymbolAddress((void**)&q_h,   g_q_h);
    cudaGetSymbolAddress((void**)&k_h,   g_k_h);
    cudaGetSymbolAddress((void**)&vt_h,  g_vt_h);
    cudaGetSymbolAddress((void**)&p_h,   g_p_h);
    cudaGetSymbolAddress((void**)&at_h,  g_at_h);
    cudaGetSymbolAddress((void**)&hln_h, g_hln_h);
    cudaGetSymbolAddress((void**)&h1_h,  g_h1_h);
    cudaGetSymbolAddress((void**)&wqkv,  g_wqkv);
    cudaGetSymbolAddress((void**)&wo,    g_wo);
    cudaGetSymbolAddress((void**)&w1,    g_w1);
    cudaGetSymbolAddress((void**)&w2,    g_w2);

    cudaFuncSetAttribute(hgemm_k, cudaFuncAttributeMaxDynamicSharedMemorySize, SMEM_BYTES);

    const int d = D_MODEL, f = D_FF, S = SEQ, B = BATCH, M = NTOK;
    const long long Sd = (long long)S * d;
    const long long SS = (long long)S * S;
    const float attn_scale = 1.0f / sqrtf((float)d);

    // 0. convert weights to fp16
    {
        long long n4;
        n4 = (long long)3 * d * d / 4; cvt_k<<<(unsigned)((n4 + 255) / 256), 256>>>(Wqkv, wqkv, n4);
        n4 = (long long)d * d / 4;     cvt_k<<<(unsigned)((n4 + 255) / 256), 256>>>(Wo,   wo,   n4);
        n4 = (long long)f * d / 4;     cvt_k<<<(unsigned)((n4 + 255) / 256), 256>>>(W1,   w1,   n4);
        n4 = (long long)d * f / 4;     cvt_k<<<(unsigned)((n4 + 255) / 256), 256>>>(W2,   w2,   n4);
    }
    // 1. LN1 (fp32 residual + half GEMM input)
    ln_k<<<M, 256>>>(src, g1, be1, xln, xln_h);
    // 2. QKV projection (half out)
    hgemm_k<<<dim3(3 * d / BN, M / BM, 1), NTHREADS, SMEM_BYTES>>>(
        xln_h, d, 0, wqkv, d, 0, qkv_h, 3 * d, 0, d, bqkv, nullptr, 1.f, 0, 0, 0, 1);
    // 3. RoPE -> half Q,K
    rope_k<<<dim3(S, B), 256>>>(qkv_h, q_h, k_h);
    // 4. V transpose -> half
    vtrans_k<<<dim3(d / 32, S / 32, B), dim3(32, 8)>>>(qkv_h, vt_h);
    // 5. scores = scale * Q K^T (fp32 out, causal block skip)
    hgemm_k<<<dim3(S / BN, S / BM, B), NTHREADS, SMEM_BYTES>>>(
        q_h, d, Sd, k_h, d, Sd, sc, S, SS, d, nullptr, nullptr, attn_scale, 0, 1, 0, 0);
    // 6. softmax -> half probs
    softmax_k<<<dim3(S, B), 256>>>(sc, p_h);
    // 7. attn = P V (K truncated; half out)
    hgemm_k<<<dim3(d / BN, S / BM, B), NTHREADS, SMEM_BYTES>>>(
        p_h, S, SS, vt_h, S, Sd, at_h, d, Sd, S, nullptr, nullptr, 1.f, 0, 0, 1, 1);
    // 8. src2 = xln + attn Wo^T + bo (fp32 out)
    hgemm_k<<<dim3(d / BN, M / BM, 1), NTHREADS, SMEM_BYTES>>>(
        at_h, d, 0, wo, d, 0, src2, d, 0, d, bo, xln, 1.f, 0, 0, 0, 0);
    // 9. LN2 -> half only
    ln_k<<<M, 256>>>(src2, g2, be2, nullptr, hln_h);
    // 10. h1 = relu(hln W1^T + b1) (half out)
    hgemm_k<<<dim3(f / BN, M / BM, 1), NTHREADS, SMEM_BYTES>>>(
        hln_h, d, 0, w1, d, 0, h1_h, f, 0, d, b1, nullptr, 1.f, 1, 0, 0, 1);
    // 11. out = src2 + h1 W2^T + b2 (fp32 out)
    hgemm_k<<<dim3(d / BN, M / BM, 1), NTHREADS, SMEM_BYTES>>>(
        h1_h, f, 0, w2, f, 0, out, d, 0, f, b2, src2, 1.f, 0, 0, 0, 0);
}

// round 11
// speedup vs baseline: 1.1148x; 1.1148x over previous
#include <cuda_runtime.h>
#include <cuda_fp16.h>
#include <math.h>
#include <stdint.h>

#define D_MODEL 2048
#define D_FF    8192
#define BATCH   4
#define SEQ     2048
#define NTOK    (BATCH * SEQ)

// ---------------------------------------------------------------------------
// Scratch
// ---------------------------------------------------------------------------
__device__ float  g_xln [(size_t)NTOK * D_MODEL];        // LN1 out fp32 (residual)
__device__ float  g_sc  [(size_t)BATCH * SEQ * SEQ];     // scores fp32
__device__ float  g_src2[(size_t)NTOK * D_MODEL];        // post-attn residual fp32
__device__ __half g_qkv_h[(size_t)NTOK * 3 * D_MODEL];   // QKV half
__device__ __half g_xln_h[(size_t)NTOK * D_MODEL];
__device__ __half g_q_h [(size_t)NTOK * D_MODEL];
__device__ __half g_k_h [(size_t)NTOK * D_MODEL];
__device__ __half g_vt_h[(size_t)NTOK * D_MODEL];        // V^T [B, d, S]
__device__ __half g_p_h [(size_t)BATCH * SEQ * SEQ];     // probs half
__device__ __half g_at_h[(size_t)NTOK * D_MODEL];        // attn half
__device__ __half g_hln_h[(size_t)NTOK * D_MODEL];
__device__ __half g_h1_h[(size_t)NTOK * D_FF];
__device__ __half g_wqkv[(size_t)3 * D_MODEL * D_MODEL];
__device__ __half g_wo  [(size_t)D_MODEL * D_MODEL];
__device__ __half g_w1  [(size_t)D_FF * D_MODEL];
__device__ __half g_w2  [(size_t)D_MODEL * D_FF];

__device__ __forceinline__ uint32_t smem_u32(const void* p) {
    uint32_t a;
    asm("{ .reg .u64 t; cvta.to.shared.u64 t, %1; cvt.u32.u64 %0, t; }" : "=r"(a) : "l"(p));
    return a;
}

#define MMA_F16(d, a, b)                                                       \
    asm volatile("mma.sync.aligned.m16n8k16.row.col.f32.f16.f16.f32 "          \
        "{%0,%1,%2,%3}, {%4,%5,%6,%7}, {%8,%9}, {%0,%1,%2,%3};"                \
        : "+f"((d)[0]), "+f"((d)[1]), "+f"((d)[2]), "+f"((d)[3])               \
        : "r"((a)[0]), "r"((a)[1]), "r"((a)[2]), "r"((a)[3]),                  \
          "r"((b)[0]), "r"((b)[1]))

#define LDM4(r0, r1, r2, r3, ad)                                               \
    asm volatile("ldmatrix.sync.aligned.m8n8.x4.shared.b16 {%0,%1,%2,%3}, [%4];" \
        : "=r"(r0), "=r"(r1), "=r"(r2), "=r"(r3) : "r"(ad))

#define CP16(dst, src) \
    asm volatile("cp.async.cg.shared.global [%0], [%1], 16;" :: "r"(dst), "l"(src))
#define CP_COMMIT() asm volatile("cp.async.commit_group;" ::: "memory")
#define CP_WAIT(n)  asm volatile("cp.async.wait_group %0;" :: "n"(n) : "memory")

// ---------------------------------------------------------------------------
// fp16 mma GEMM: C[M,N] = scale*(A @ B^T) [+bias][+res][relu]
// A:[M,K] half row-major, B:[N,K] half row-major. M,N mult 128, K mult 64.
// CTA 128x128x64, 4 warps (2x2), warp 64x64, m16n8k16, ldmatrix.x4 frags.
// 3-stage cp.async, 2 CTAs/SM. Row pitch 144 B (conflict-free).
// ---------------------------------------------------------------------------
#define BK        64
#define PITCH_B   144                    // bytes per smem row
#define TILE_B    (128 * PITCH_B)        // 18432 B
#define STAGE_B   (2 * TILE_B)           // 36864 B
#define STAGES    3
#define SMEM_BYTES (STAGES * STAGE_B)    // 110592 B
#define NTHREADS  128

__global__ __launch_bounds__(NTHREADS)
void hgemm_k(const __half* __restrict__ A, int lda, long long sA,
             const __half* __restrict__ B, int ldb, long long sB,
             void*         __restrict__ Cv, int ldc, long long sC,
             int K,
             const float* __restrict__ bias,
             const float* __restrict__ res,
             float scale, int relu, int causal_skip, int klimit, int half_out)
{
    const int bm = blockIdx.y * 128;
    const int bn = blockIdx.x * 128;
    if (causal_skip && bn > bm) return;

    extern __shared__ float sm[];
    const uint32_t sbase = smem_u32(sm);

    const int tid = threadIdx.x;
    const int wid = tid >> 5;
    const int lane = tid & 31;
    const int g   = lane >> 2;
    const int tig = lane & 3;
    const int wm  = wid >> 1;
    const int wn  = wid & 1;
    const uint32_t lrow = (lane & 7) + ((lane >> 3) & 1) * 8;
    const uint32_t lk16 = (lane >> 4) * 16;

    const long long bz = blockIdx.z;
    A += bz * sA;  B += bz * sB;
    const float* R = res ? res + bz * sC : nullptr;

    int Keff = K;
    if (klimit) { int kl = bm + 128; Keff = (kl < K) ? kl : K; }
    const int KT = Keff / BK;

    const __half* Abase = A + (long long)bm * lda;
    const __half* Bbase = B + (long long)bn * ldb;

#define ISSUE(kt_, st_) do {                                                   \
    const int _k0 = (kt_) * BK;                                                \
    const uint32_t _so = (uint32_t)(st_) * STAGE_B;                            \
    _Pragma("unroll")                                                          \
    for (int t = 0; t < 8; t++) {                                              \
        int c = tid + t * NTHREADS;                                            \
        int row = c >> 3, chk = c & 7;                                         \
        uint32_t w = (uint32_t)row * PITCH_B + (uint32_t)(chk << 4);           \
        CP16(sbase + _so + w,          Abase + (long long)row * lda + _k0 + (chk << 3)); \
        CP16(sbase + _so + TILE_B + w, Bbase + (long long)row * ldb + _k0 + (chk << 3)); \
    }                                                                          \
} while (0)

    float acc[4][8][4];
#pragma unroll
    for (int i = 0; i < 4; i++)
#pragma unroll
        for (int j = 0; j < 8; j++)
#pragma unroll
            for (int r = 0; r < 4; r++) acc[i][j][r] = 0.f;

#pragma unroll
    for (int s = 0; s < STAGES - 1; s++) { ISSUE(s, s); CP_COMMIT(); }
    CP_WAIT(STAGES - 2);
    __syncthreads();

    const uint32_t aAddr0 = sbase + (wm * 64 + lrow) * PITCH_B + lk16;
    const uint32_t bAddr0 = sbase + TILE_B + (wn * 64 + lrow) * PITCH_B + lk16;

    for (int kt = 0; kt < KT; kt++) {
        const int next = kt + STAGES - 1;
        if (next < KT) ISSUE(next, next % STAGES);
        CP_COMMIT();

        const uint32_t so = (uint32_t)(kt % STAGES) * STAGE_B;

#pragma unroll
        for (int ks = 0; ks < 4; ks++) {
            uint32_t a[4][4], b[8][2];
#pragma unroll
            for (int mf = 0; mf < 4; mf++)
                LDM4(a[mf][0], a[mf][1], a[mf][2], a[mf][3],
                     aAddr0 + so + (uint32_t)(mf * 16) * PITCH_B + ks * 32);
#pragma unroll
            for (int np = 0; np < 4; np++)
                LDM4(b[2 * np][0], b[2 * np + 1][0], b[2 * np][1], b[2 * np + 1][1],
                     bAddr0 + so + (uint32_t)(np * 16) * PITCH_B + ks * 32);
#pragma unroll
            for (int mf = 0; mf < 4; mf++)
#pragma unroll
                for (int nf = 0; nf < 8; nf++)
                    MMA_F16(acc[mf][nf], a[mf], b[nf]);
        }
        CP_WAIT(STAGES - 2);
        __syncthreads();
    }

    // epilogue: c0=(g,2tig) c1=(g,2tig+1) c2=(g+8,2tig) c3=(g+8,2tig+1)
    float*  Cf = (float*)Cv  + bz * sC;
    __half* Ch = (__half*)Cv + bz * sC;
#pragma unroll
    for (int mf = 0; mf < 4; mf++) {
        const int m0 = bm + wm * 64 + mf * 16 + g;
#pragma unroll
        for (int nf = 0; nf < 8; nf++) {
            const int n0 = bn + wn * 64 + nf * 8 + 2 * tig;
            float2 v0, v1;
            v0.x = acc[mf][nf][0] * scale; v0.y = acc[mf][nf][1] * scale;
            v1.x = acc[mf][nf][2] * scale; v1.y = acc[mf][nf][3] * scale;
            if (bias) {
                float bx = __ldg(bias + n0), by = __ldg(bias + n0 + 1);
                v0.x += bx; v0.y += by; v1.x += bx; v1.y += by;
            }
            if (R) {
                float2 r0 = *(const float2*)(R + (long long)m0 * ldc + n0);
                float2 r1 = *(const float2*)(R + (long long)(m0 + 8) * ldc + n0);
                v0.x += r0.x; v0.y += r0.y; v1.x += r1.x; v1.y += r1.y;
            }
            if (relu) {
                v0.x = fmaxf(v0.x, 0.f); v0.y = fmaxf(v0.y, 0.f);
                v1.x = fmaxf(v1.x, 0.f); v1.y = fmaxf(v1.y, 0.f);
            }
            if (half_out) {
                *(__half2*)(Ch + (long long)m0 * ldc + n0)       = __floats2half2_rn(v0.x, v0.y);
                *(__half2*)(Ch + (long long)(m0 + 8) * ldc + n0) = __floats2half2_rn(v1.x, v1.y);
            } else {
                *(float2*)(Cf + (long long)m0 * ldc + n0)       = v0;
                *(float2*)(Cf + (long long)(m0 + 8) * ldc + n0) = v1;
            }
        }
    }
}

// ---------------------------------------------------------------------------
// fp32 -> fp16 conversion (weights)
// ---------------------------------------------------------------------------
__global__ __launch_bounds__(256)
void cvt_k(const float* __restrict__ x, __half* __restrict__ y, long long n4)
{
    long long i = (long long)blockIdx.x * 256 + threadIdx.x;
    if (i < n4) {
        float4 v = ((const float4*)x)[i];
        __half2 h0 = __floats2half2_rn(v.x, v.y);
        __half2 h1 = __floats2half2_rn(v.z, v.w);
        ((uint2*)y)[i] = make_uint2(*(uint32_t*)&h0, *(uint32_t*)&h1);
    }
}

// ---------------------------------------------------------------------------
// LayerNorm: optional fp32 out (residual) + half out (GEMM input)
// ---------------------------------------------------------------------------
__global__ __launch_bounds__(256)
void ln_k(const float* __restrict__ x, const float* __restrict__ g,
          const float* __restrict__ b, float* __restrict__ y, __half* __restrict__ yh)
{
    const int D = D_MODEL;
    const long long row = blockIdx.x;
    const float* xr = x + row * D;
    __half*      hr = yh + row * D;
    const int tid = threadIdx.x;

    __shared__ float sh[256];
    float v[8];
    float s = 0.f;
#pragma unroll
    for (int i = 0; i < 8; i++) { v[i] = xr[tid + i * 256]; s += v[i]; }
    sh[tid] = s; __syncthreads();
    for (int o = 128; o > 0; o >>= 1) { if (tid < o) sh[tid] += sh[tid + o]; __syncthreads(); }
    const float mean = sh[0] * (1.f / D);
    __syncthreads();

    s = 0.f;
#pragma unroll
    for (int i = 0; i < 8; i++) { float d = v[i] - mean; s += d * d; }
    sh[tid] = s; __syncthreads();
    for (int o = 128; o > 0; o >>= 1) { if (tid < o) sh[tid] += sh[tid + o]; __syncthreads(); }
    const float r = rsqrtf(sh[0] * (1.f / D) + 1e-5f);

    float* yr = y ? y + row * D : nullptr;
#pragma unroll
    for (int i = 0; i < 8; i++) {
        int j = tid + i * 256;
        float o = (v[i] - mean) * r * __ldg(g + j) + __ldg(b + j);
        if (yr) yr[j] = o;
        hr[j] = __float2half_rn(o);
    }
}

// ---------------------------------------------------------------------------
// RoPE (reference-exact trig-of-trig), half in / half out
// ---------------------------------------------------------------------------
__global__ __launch_bounds__(256)
void rope_k(const __half* __restrict__ qkv, __half* __restrict__ Qo, __half* __restrict__ Ko)
{
    const int d = D_MODEL, half = D_MODEL / 2;
    const int t = blockIdx.x, b = blockIdx.y;
    const long long rq = ((long long)b * SEQ + t) * (3 * D_MODEL);
    const __half* Q = qkv + rq;
    const __half* K = qkv + rq + d;
    const long long ro = ((long long)b * SEQ + t) * d;
    const float pos = (float)t;
    const float l2c = -13.28771238f / 1024.f;   // -log2(10000)/1024

#pragma unroll
    for (int i = 0; i < 8; i++) {
        int j = threadIdx.x + i * 256;
        int fidx = (j < half) ? j : (j - half);
        float invf = exp2f(l2c * (float)fidx);
        float sp = pos * invf;
        float e = (j < half) ? sinf(sp) : cosf(sp);
        float c = cosf(e), s = sinf(e);
        float rqv, rkv;
        if (j < half) { rqv = -__half2float(Q[2 * j]);
                        rkv = -__half2float(K[2 * j]); }
        else          { rqv =  __half2float(Q[2 * (j - half) + 1]);
                        rkv =  __half2float(K[2 * (j - half) + 1]); }
        Qo[ro + j] = __float2half_rn(__half2float(Q[j]) * c + rqv * s);
        Ko[ro + j] = __float2half_rn(__half2float(K[j]) * c - rkv * s);
    }
}

// ---------------------------------------------------------------------------
// V transpose (half in/out): vt[b, n, s] = qkv[b, s, 2d + n]
// ---------------------------------------------------------------------------
__global__ __launch_bounds__(256)
void vtrans_k(const __half* __restrict__ qkv, __half* __restrict__ vt)
{
    __shared__ __half t[32][33];
    const int b = blockIdx.z;
    const int s0 = blockIdx.y * 32, n0 = blockIdx.x * 32;
    const int x = threadIdx.x, y = threadIdx.y;
#pragma unroll
    for (int i = 0; i < 32; i += 8)
        t[y + i][x] = qkv[((long long)b * SEQ + s0 + y + i) * (3 * D_MODEL) + 2 * D_MODEL + n0 + x];
    __syncthreads();
#pragma unroll
    for (int i = 0; i < 32; i += 8)
        vt[((long long)b * D_MODEL + n0 + y + i) * SEQ + s0 + x] = t[x][y + i];
}

// ---------------------------------------------------------------------------
// Causal softmax: fp32 scores in, half probs out (cols < ceil128(q+1))
// ---------------------------------------------------------------------------
__global__ __launch_bounds__(256)
void softmax_k(const float* __restrict__ S_, __half* __restrict__ P)
{
    const int S = SEQ;
    const int q = blockIdx.x, b = blockIdx.y;
    const float* row = S_ + ((long long)b * S + q) * S;
    __half* prow = P + ((long long)b * S + q) * S;
    const int n = q + 1;
    const int klim = ((q >> 7) + 1) << 7;
    const int tid = threadIdx.x;
    __shared__ float sh[256];

    float v[8];
    float mx = -3.402823e38f;
#pragma unroll
    for (int i = 0; i < 8; i++) {
        int j = tid + i * 256;
        v[i] = (j < n) ? row[j] : -3.402823e38f;
        mx = fmaxf(mx, v[i]);
    }
    sh[tid] = mx; __syncthreads();
    for (int o = 128; o > 0; o >>= 1) { if (tid < o) sh[tid] = fmaxf(sh[tid], sh[tid + o]); __syncthreads(); }
    mx = sh[0]; __syncthreads();

    float sum = 0.f;
#pragma unroll
    for (int i = 0; i < 8; i++) {
        int j = tid + i * 256;
        v[i] = (j < n) ? expf(v[i] - mx) : 0.f;
        sum += v[i];
    }
    sh[tid] = sum; __syncthreads();
    for (int o = 128; o > 0; o >>= 1) { if (tid < o) sh[tid] += sh[tid + o]; __syncthreads(); }
    const float inv = 1.f / sh[0];

#pragma unroll
    for (int i = 0; i < 8; i++) {
        int j = tid + i * 256;
        if (j < klim) prow[j] = __float2half_rn(v[i] * inv);
    }
}

// ---------------------------------------------------------------------------
// Launch
// ---------------------------------------------------------------------------
extern "C" void kernel_launch(void* const* d_in, const int* in_sizes, int n_in,
                              void* d_out, int out_size)
{
    const float* src  = (const float*)d_in[0];
    const float* Wqkv = (const float*)d_in[1];
    const float* bqkv = (const float*)d_in[2];
    const float* Wo   = (const float*)d_in[3];
    const float* bo   = (const float*)d_in[4];
    const float* W1   = (const float*)d_in[5];
    const float* b1   = (const float*)d_in[6];
    const float* W2   = (const float*)d_in[7];
    const float* b2   = (const float*)d_in[8];
    const float* g1   = (const float*)d_in[9];
    const float* be1  = (const float*)d_in[10];
    const float* g2   = (const float*)d_in[11];
    const float* be2  = (const float*)d_in[12];
    float* out = (float*)d_out;

    float *xln, *sc, *src2;
    __half *qkv_h, *xln_h, *q_h, *k_h, *vt_h, *p_h, *at_h, *hln_h, *h1_h;
    __half *wqkv, *wo, *w1, *w2;
    cudaGetSymbolAddress((void**)&xln,   g_xln);
    cudaGetSymbolAddress((void**)&sc,    g_sc);
    cudaGetSymbolAddress((void**)&src2,  g_src2);
    cudaGetSymbolAddress((void**)&qkv_h, g_qkv_h);
    cudaGetSymbolAddress((void**)&xln_h, g_xln_h);
    cudaGetSymbolAddress((void**)&q_h,   g_q_h);
    cudaGetSymbolAddress((void**)&k_h,   g_k_h);
    cudaGetSymbolAddress((void**)&vt_h,  g_vt_h);
    cudaGetSymbolAddress((void**)&p_h,   g_p_h);
    cudaGetSymbolAddress((void**)&at_h,  g_at_h);
    cudaGetSymbolAddress((void**)&hln_h, g_hln_h);
    cudaGetSymbolAddress((void**)&h1_h,  g_h1_h);
    cudaGetSymbolAddress((void**)&wqkv,  g_wqkv);
    cudaGetSymbolAddress((void**)&wo,    g_wo);
    cudaGetSymbolAddress((void**)&w1,    g_w1);
    cudaGetSymbolAddress((void**)&w2,    g_w2);

    cudaFuncSetAttribute(hgemm_k, cudaFuncAttributeMaxDynamicSharedMemorySize, SMEM_BYTES);

    const int d = D_MODEL, f = D_FF, S = SEQ, B = BATCH, M = NTOK;
    const long long Sd = (long long)S * d;
    const long long SS = (long long)S * S;
    const float attn_scale = 1.0f / sqrtf((float)d);

    // 0. convert weights to fp16
    {
        long long n4;
        n4 = (long long)3 * d * d / 4; cvt_k<<<(unsigned)((n4 + 255) / 256), 256>>>(Wqkv, wqkv, n4);
        n4 = (long long)d * d / 4;     cvt_k<<<(unsigned)((n4 + 255) / 256), 256>>>(Wo,   wo,   n4);
        n4 = (long long)f * d / 4;     cvt_k<<<(unsigned)((n4 + 255) / 256), 256>>>(W1,   w1,   n4);
        n4 = (long long)d * f / 4;     cvt_k<<<(unsigned)((n4 + 255) / 256), 256>>>(W2,   w2,   n4);
    }
    // 1. LN1 (fp32 residual + half GEMM input)
    ln_k<<<M, 256>>>(src, g1, be1, xln, xln_h);
    // 2. QKV projection (half out)
    hgemm_k<<<dim3(3 * d / 128, M / 128, 1), NTHREADS, SMEM_BYTES>>>(
        xln_h, d, 0, wqkv, d, 0, qkv_h, 3 * d, 0, d, bqkv, nullptr, 1.f, 0, 0, 0, 1);
    // 3. RoPE -> half Q,K
    rope_k<<<dim3(S, B), 256>>>(qkv_h, q_h, k_h);
    // 4. V transpose -> half
    vtrans_k<<<dim3(d / 32, S / 32, B), dim3(32, 8)>>>(qkv_h, vt_h);
    // 5. scores = scale * Q K^T (fp32 out, causal block skip)
    hgemm_k<<<dim3(S / 128, S / 128, B), NTHREADS, SMEM_BYTES>>>(
        q_h, d, Sd, k_h, d, Sd, sc, S, SS, d, nullptr, nullptr, attn_scale, 0, 1, 0, 0);
    // 6. softmax -> half probs
    softmax_k<<<dim3(S, B), 256>>>(sc, p_h);
    // 7. attn = P V (K truncated; half out)
    hgemm_k<<<dim3(d / 128, S / 128, B), NTHREADS, SMEM_BYTES>>>(
        p_h, S, SS, vt_h, S, Sd, at_h, d, Sd, S, nullptr, nullptr, 1.f, 0, 0, 1, 1);
    // 8. src2 = xln + attn Wo^T + bo (fp32 out)
    hgemm_k<<<dim3(d / 128, M / 128, 1), NTHREADS, SMEM_BYTES>>>(
        at_h, d, 0, wo, d, 0, src2, d, 0, d, bo, xln, 1.f, 0, 0, 0, 0);
    // 9. LN2 -> half only
    ln_k<<<M, 256>>>(src2, g2, be2, nullptr, hln_h);
    // 10. h1 = relu(hln W1^T + b1) (half out)
    hgemm_k<<<dim3(f / 128, M / 128, 1), NTHREADS, SMEM_BYTES>>>(
        hln_h, d, 0, w1, d, 0, h1_h, f, 0, d, b1, nullptr, 1.f, 1, 0, 0, 1);
    // 11. out = src2 + h1 W2^T + b2 (fp32 out)
    hgemm_k<<<dim3(d / 128, M / 128, 1), NTHREADS, SMEM_BYTES>>>(
        h1_h, f, 0, w2, f, 0, out, d, 0, f, b2, src2, 1.f, 0, 0, 0, 0);
}

// round 12
// speedup vs baseline: 1.1669x; 1.0468x over previous
#include <cuda_runtime.h>
#include <cuda_fp16.h>
#include <math.h>
#include <stdint.h>

#define D_MODEL 2048
#define D_FF    8192
#define BATCH   4
#define SEQ     2048
#define NTOK    (BATCH * SEQ)

// ---------------------------------------------------------------------------
// Scratch
// ---------------------------------------------------------------------------
__device__ float  g_xln [(size_t)NTOK * D_MODEL];        // LN1 out fp32 (residual)
__device__ float  g_sc  [(size_t)BATCH * SEQ * SEQ];     // scores fp32
__device__ float  g_src2[(size_t)NTOK * D_MODEL];        // post-attn residual fp32
__device__ __half g_qkv_h[(size_t)NTOK * 3 * D_MODEL];   // QKV half
__device__ __half g_xln_h[(size_t)NTOK * D_MODEL];
__device__ __half g_q_h [(size_t)NTOK * D_MODEL];
__device__ __half g_k_h [(size_t)NTOK * D_MODEL];
__device__ __half g_vt_h[(size_t)NTOK * D_MODEL];        // V^T [B, d, S]
__device__ __half g_p_h [(size_t)BATCH * SEQ * SEQ];     // probs half
__device__ __half g_at_h[(size_t)NTOK * D_MODEL];        // attn half
__device__ __half g_hln_h[(size_t)NTOK * D_MODEL];
__device__ __half g_h1_h[(size_t)NTOK * D_FF];
__device__ __half g_wqkv[(size_t)3 * D_MODEL * D_MODEL];
__device__ __half g_wo  [(size_t)D_MODEL * D_MODEL];
__device__ __half g_w1  [(size_t)D_FF * D_MODEL];
__device__ __half g_w2  [(size_t)D_MODEL * D_FF];

__device__ __forceinline__ uint32_t smem_u32(const void* p) {
    uint32_t a;
    asm("{ .reg .u64 t; cvta.to.shared.u64 t, %1; cvt.u32.u64 %0, t; }" : "=r"(a) : "l"(p));
    return a;
}

#define MMA_F16(d, a, b)                                                       \
    asm volatile("mma.sync.aligned.m16n8k16.row.col.f32.f16.f16.f32 "          \
        "{%0,%1,%2,%3}, {%4,%5,%6,%7}, {%8,%9}, {%0,%1,%2,%3};"                \
        : "+f"((d)[0]), "+f"((d)[1]), "+f"((d)[2]), "+f"((d)[3])               \
        : "r"((a)[0]), "r"((a)[1]), "r"((a)[2]), "r"((a)[3]),                  \
          "r"((b)[0]), "r"((b)[1]))

#define LDM4(r0, r1, r2, r3, ad)                                               \
    asm volatile("ldmatrix.sync.aligned.m8n8.x4.shared.b16 {%0,%1,%2,%3}, [%4];" \
        : "=r"(r0), "=r"(r1), "=r"(r2), "=r"(r3) : "r"(ad))

#define CP16(dst, src) \
    asm volatile("cp.async.cg.shared.global [%0], [%1], 16;" :: "r"(dst), "l"(src))
#define CP_COMMIT() asm volatile("cp.async.commit_group;" ::: "memory")
#define CP_WAIT(n)  asm volatile("cp.async.wait_group %0;" :: "n"(n) : "memory")

// ---------------------------------------------------------------------------
// fp16 mma GEMM: C[M,N] = scale*(A @ B^T) [+bias][+res][relu]
// A:[M,K] half row-major, B:[N,K] half row-major. M,N mult 128, K mult 64.
// CTA 128x128x64, 8 warps (2m x 4n), warp 64x32, m16n8k16, ldmatrix.x4.
// 3-stage cp.async, 2 CTAs/SM (16 warps/SM -> 4/SMSP for latency hiding).
// Row pitch 144 B (conflict-free).
// ---------------------------------------------------------------------------
#define BK        64
#define PITCH_B   144                    // bytes per smem row
#define TILE_B    (128 * PITCH_B)        // 18432 B
#define STAGE_B   (2 * TILE_B)           // 36864 B
#define STAGES    3
#define SMEM_BYTES (STAGES * STAGE_B)    // 110592 B
#define NTHREADS  256

__global__ __launch_bounds__(NTHREADS)
void hgemm_k(const __half* __restrict__ A, int lda, long long sA,
             const __half* __restrict__ B, int ldb, long long sB,
             void*         __restrict__ Cv, int ldc, long long sC,
             int K,
             const float* __restrict__ bias,
             const float* __restrict__ res,
             float scale, int relu, int causal_skip, int klimit, int half_out)
{
    const int bm = blockIdx.y * 128;
    const int bn = blockIdx.x * 128;
    if (causal_skip && bn > bm) return;

    extern __shared__ float sm[];
    const uint32_t sbase = smem_u32(sm);

    const int tid = threadIdx.x;
    const int wid = tid >> 5;
    const int lane = tid & 31;
    const int g   = lane >> 2;
    const int tig = lane & 3;
    const int wm  = wid >> 2;            // 0..1
    const int wn  = wid & 3;             // 0..3
    const uint32_t lrow = (lane & 7) + ((lane >> 3) & 1) * 8;
    const uint32_t lk16 = (lane >> 4) * 16;

    const long long bz = blockIdx.z;
    A += bz * sA;  B += bz * sB;
    const float* R = res ? res + bz * sC : nullptr;

    int Keff = K;
    if (klimit) { int kl = bm + 128; Keff = (kl < K) ? kl : K; }
    const int KT = Keff / BK;

    const __half* Abase = A + (long long)bm * lda;
    const __half* Bbase = B + (long long)bn * ldb;

#define ISSUE(kt_, st_) do {                                                   \
    const int _k0 = (kt_) * BK;                                                \
    const uint32_t _so = (uint32_t)(st_) * STAGE_B;                            \
    _Pragma("unroll")                                                          \
    for (int t = 0; t < 4; t++) {                                              \
        int c = tid + t * NTHREADS;                                            \
        int row = c >> 3, chk = c & 7;                                         \
        uint32_t w = (uint32_t)row * PITCH_B + (uint32_t)(chk << 4);           \
        CP16(sbase + _so + w,          Abase + (long long)row * lda + _k0 + (chk << 3)); \
        CP16(sbase + _so + TILE_B + w, Bbase + (long long)row * ldb + _k0 + (chk << 3)); \
    }                                                                          \
} while (0)

    float acc[4][4][4];
#pragma unroll
    for (int i = 0; i < 4; i++)
#pragma unroll
        for (int j = 0; j < 4; j++)
#pragma unroll
            for (int r = 0; r < 4; r++) acc[i][j][r] = 0.f;

#pragma unroll
    for (int s = 0; s < STAGES - 1; s++) { ISSUE(s, s); CP_COMMIT(); }
    CP_WAIT(STAGES - 2);
    __syncthreads();

    const uint32_t aAddr0 = sbase + (wm * 64 + lrow) * PITCH_B + lk16;
    const uint32_t bAddr0 = sbase + TILE_B + (wn * 32 + lrow) * PITCH_B + lk16;

    for (int kt = 0; kt < KT; kt++) {
        const int next = kt + STAGES - 1;
        if (next < KT) ISSUE(next, next % STAGES);
        CP_COMMIT();

        const uint32_t so = (uint32_t)(kt % STAGES) * STAGE_B;

#pragma unroll
        for (int ks = 0; ks < 4; ks++) {
            uint32_t a[4][4], b[4][2];
#pragma unroll
            for (int mf = 0; mf < 4; mf++)
                LDM4(a[mf][0], a[mf][1], a[mf][2], a[mf][3],
                     aAddr0 + so + (uint32_t)(mf * 16) * PITCH_B + ks * 32);
#pragma unroll
            for (int np = 0; np < 2; np++)
                LDM4(b[2 * np][0], b[2 * np + 1][0], b[2 * np][1], b[2 * np + 1][1],
                     bAddr0 + so + (uint32_t)(np * 16) * PITCH_B + ks * 32);
#pragma unroll
            for (int mf = 0; mf < 4; mf++)
#pragma unroll
                for (int nf = 0; nf < 4; nf++)
                    MMA_F16(acc[mf][nf], a[mf], b[nf]);
        }
        CP_WAIT(STAGES - 2);
        __syncthreads();
    }

    // epilogue: c0=(g,2tig) c1=(g,2tig+1) c2=(g+8,2tig) c3=(g+8,2tig+1)
    float*  Cf = (float*)Cv  + bz * sC;
    __half* Ch = (__half*)Cv + bz * sC;
#pragma unroll
    for (int mf = 0; mf < 4; mf++) {
        const int m0 = bm + wm * 64 + mf * 16 + g;
#pragma unroll
        for (int nf = 0; nf < 4; nf++) {
            const int n0 = bn + wn * 32 + nf * 8 + 2 * tig;
            float2 v0, v1;
            v0.x = acc[mf][nf][0] * scale; v0.y = acc[mf][nf][1] * scale;
            v1.x = acc[mf][nf][2] * scale; v1.y = acc[mf][nf][3] * scale;
            if (bias) {
                float bx = __ldg(bias + n0), by = __ldg(bias + n0 + 1);
                v0.x += bx; v0.y += by; v1.x += bx; v1.y += by;
            }
            if (R) {
                float2 r0 = *(const float2*)(R + (long long)m0 * ldc + n0);
                float2 r1 = *(const float2*)(R + (long long)(m0 + 8) * ldc + n0);
                v0.x += r0.x; v0.y += r0.y; v1.x += r1.x; v1.y += r1.y;
            }
            if (relu) {
                v0.x = fmaxf(v0.x, 0.f); v0.y = fmaxf(v0.y, 0.f);
                v1.x = fmaxf(v1.x, 0.f); v1.y = fmaxf(v1.y, 0.f);
            }
            if (half_out) {
                *(__half2*)(Ch + (long long)m0 * ldc + n0)       = __floats2half2_rn(v0.x, v0.y);
                *(__half2*)(Ch + (long long)(m0 + 8) * ldc + n0) = __floats2half2_rn(v1.x, v1.y);
            } else {
                *(float2*)(Cf + (long long)m0 * ldc + n0)       = v0;
                *(float2*)(Cf + (long long)(m0 + 8) * ldc + n0) = v1;
            }
        }
    }
}

// ---------------------------------------------------------------------------
// fp32 -> fp16 conversion (weights)
// ---------------------------------------------------------------------------
__global__ __launch_bounds__(256)
void cvt_k(const float* __restrict__ x, __half* __restrict__ y, long long n4)
{
    long long i = (long long)blockIdx.x * 256 + threadIdx.x;
    if (i < n4) {
        float4 v = ((const float4*)x)[i];
        __half2 h0 = __floats2half2_rn(v.x, v.y);
        __half2 h1 = __floats2half2_rn(v.z, v.w);
        ((uint2*)y)[i] = make_uint2(*(uint32_t*)&h0, *(uint32_t*)&h1);
    }
}

// ---------------------------------------------------------------------------
// LayerNorm: optional fp32 out (residual) + half out (GEMM input)
// ---------------------------------------------------------------------------
__global__ __launch_bounds__(256)
void ln_k(const float* __restrict__ x, const float* __restrict__ g,
          const float* __restrict__ b, float* __restrict__ y, __half* __restrict__ yh)
{
    const int D = D_MODEL;
    const long long row = blockIdx.x;
    const float* xr = x + row * D;
    __half*      hr = yh + row * D;
    const int tid = threadIdx.x;

    __shared__ float sh[256];
    float v[8];
    float s = 0.f;
#pragma unroll
    for (int i = 0; i < 8; i++) { v[i] = xr[tid + i * 256]; s += v[i]; }
    sh[tid] = s; __syncthreads();
    for (int o = 128; o > 0; o >>= 1) { if (tid < o) sh[tid] += sh[tid + o]; __syncthreads(); }
    const float mean = sh[0] * (1.f / D);
    __syncthreads();

    s = 0.f;
#pragma unroll
    for (int i = 0; i < 8; i++) { float d = v[i] - mean; s += d * d; }
    sh[tid] = s; __syncthreads();
    for (int o = 128; o > 0; o >>= 1) { if (tid < o) sh[tid] += sh[tid + o]; __syncthreads(); }
    const float r = rsqrtf(sh[0] * (1.f / D) + 1e-5f);

    float* yr = y ? y + row * D : nullptr;
#pragma unroll
    for (int i = 0; i < 8; i++) {
        int j = tid + i * 256;
        float o = (v[i] - mean) * r * __ldg(g + j) + __ldg(b + j);
        if (yr) yr[j] = o;
        hr[j] = __float2half_rn(o);
    }
}

// ---------------------------------------------------------------------------
// RoPE (reference-exact trig-of-trig), half in / half out
// ---------------------------------------------------------------------------
__global__ __launch_bounds__(256)
void rope_k(const __half* __restrict__ qkv, __half* __restrict__ Qo, __half* __restrict__ Ko)
{
    const int d = D_MODEL, half = D_MODEL / 2;
    const int t = blockIdx.x, b = blockIdx.y;
    const long long rq = ((long long)b * SEQ + t) * (3 * D_MODEL);
    const __half* Q = qkv + rq;
    const __half* K = qkv + rq + d;
    const long long ro = ((long long)b * SEQ + t) * d;
    const float pos = (float)t;
    const float l2c = -13.28771238f / 1024.f;   // -log2(10000)/1024

#pragma unroll
    for (int i = 0; i < 8; i++) {
        int j = threadIdx.x + i * 256;
        int fidx = (j < half) ? j : (j - half);
        float invf = exp2f(l2c * (float)fidx);
        float sp = pos * invf;
        float e = (j < half) ? sinf(sp) : cosf(sp);
        float c = cosf(e), s = sinf(e);
        float rqv, rkv;
        if (j < half) { rqv = -__half2float(Q[2 * j]);
                        rkv = -__half2float(K[2 * j]); }
        else          { rqv =  __half2float(Q[2 * (j - half) + 1]);
                        rkv =  __half2float(K[2 * (j - half) + 1]); }
        Qo[ro + j] = __float2half_rn(__half2float(Q[j]) * c + rqv * s);
        Ko[ro + j] = __float2half_rn(__half2float(K[j]) * c - rkv * s);
    }
}

// ---------------------------------------------------------------------------
// V transpose (half in/out): vt[b, n, s] = qkv[b, s, 2d + n]
// ---------------------------------------------------------------------------
__global__ __launch_bounds__(256)
void vtrans_k(const __half* __restrict__ qkv, __half* __restrict__ vt)
{
    __shared__ __half t[32][33];
    const int b = blockIdx.z;
    const int s0 = blockIdx.y * 32, n0 = blockIdx.x * 32;
    const int x = threadIdx.x, y = threadIdx.y;
#pragma unroll
    for (int i = 0; i < 32; i += 8)
        t[y + i][x] = qkv[((long long)b * SEQ + s0 + y + i) * (3 * D_MODEL) + 2 * D_MODEL + n0 + x];
    __syncthreads();
#pragma unroll
    for (int i = 0; i < 32; i += 8)
        vt[((long long)b * D_MODEL + n0 + y + i) * SEQ + s0 + x] = t[x][y + i];
}

// ---------------------------------------------------------------------------
// Causal softmax: fp32 scores in, half probs out (cols < ceil128(q+1))
// ---------------------------------------------------------------------------
__global__ __launch_bounds__(256)
void softmax_k(const float* __restrict__ S_, __half* __restrict__ P)
{
    const int S = SEQ;
    const int q = blockIdx.x, b = blockIdx.y;
    const float* row = S_ + ((long long)b * S + q) * S;
    __half* prow = P + ((long long)b * S + q) * S;
    const int n = q + 1;
    const int klim = ((q >> 7) + 1) << 7;
    const int tid = threadIdx.x;
    __shared__ float sh[256];

    float v[8];
    float mx = -3.402823e38f;
#pragma unroll
    for (int i = 0; i < 8; i++) {
        int j = tid + i * 256;
        v[i] = (j < n) ? row[j] : -3.402823e38f;
        mx = fmaxf(mx, v[i]);
    }
    sh[tid] = mx; __syncthreads();
    for (int o = 128; o > 0; o >>= 1) { if (tid < o) sh[tid] = fmaxf(sh[tid], sh[tid + o]); __syncthreads(); }
    mx = sh[0]; __syncthreads();

    float sum = 0.f;
#pragma unroll
    for (int i = 0; i < 8; i++) {
        int j = tid + i * 256;
        v[i] = (j < n) ? expf(v[i] - mx) : 0.f;
        sum += v[i];
    }
    sh[tid] = sum; __syncthreads();
    for (int o = 128; o > 0; o >>= 1) { if (tid < o) sh[tid] += sh[tid + o]; __syncthreads(); }
    const float inv = 1.f / sh[0];

#pragma unroll
    for (int i = 0; i < 8; i++) {
        int j = tid + i * 256;
        if (j < klim) prow[j] = __float2half_rn(v[i] * inv);
    }
}

// ---------------------------------------------------------------------------
// Launch
// ---------------------------------------------------------------------------
extern "C" void kernel_launch(void* const* d_in, const int* in_sizes, int n_in,
                              void* d_out, int out_size)
{
    const float* src  = (const float*)d_in[0];
    const float* Wqkv = (const float*)d_in[1];
    const float* bqkv = (const float*)d_in[2];
    const float* Wo   = (const float*)d_in[3];
    const float* bo   = (const float*)d_in[4];
    const float* W1   = (const float*)d_in[5];
    const float* b1   = (const float*)d_in[6];
    const float* W2   = (const float*)d_in[7];
    const float* b2   = (const float*)d_in[8];
    const float* g1   = (const float*)d_in[9];
    const float* be1  = (const float*)d_in[10];
    const float* g2   = (const float*)d_in[11];
    const float* be2  = (const float*)d_in[12];
    float* out = (float*)d_out;

    float *xln, *sc, *src2;
    __half *qkv_h, *xln_h, *q_h, *k_h, *vt_h, *p_h, *at_h, *hln_h, *h1_h;
    __half *wqkv, *wo, *w1, *w2;
    cudaGetSymbolAddress((void**)&xln,   g_xln);
    cudaGetSymbolAddress((void**)&sc,    g_sc);
    cudaGetSymbolAddress((void**)&src2,  g_src2);
    cudaGetSymbolAddress((void**)&qkv_h, g_qkv_h);
    cudaGetSymbolAddress((void**)&xln_h, g_xln_h);
    cudaGetSymbolAddress((void**)&q_h,   g_q_h);
    cudaGetSymbolAddress((void**)&k_h,   g_k_h);
    cudaGetSymbolAddress((void**)&vt_h,  g_vt_h);
    cudaGetSymbolAddress((void**)&p_h,   g_p_h);
    cudaGetSymbolAddress((void**)&at_h,  g_at_h);
    cudaGetSymbolAddress((void**)&hln_h, g_hln_h);
    cudaGetSymbolAddress((void**)&h1_h,  g_h1_h);
    cudaGetSymbolAddress((void**)&wqkv,  g_wqkv);
    cudaGetSymbolAddress((void**)&wo,    g_wo);
    cudaGetSymbolAddress((void**)&w1,    g_w1);
    cudaGetSymbolAddress((void**)&w2,    g_w2);

    cudaFuncSetAttribute(hgemm_k, cudaFuncAttributeMaxDynamicSharedMemorySize, SMEM_BYTES);

    const int d = D_MODEL, f = D_FF, S = SEQ, B = BATCH, M = NTOK;
    const long long Sd = (long long)S * d;
    const long long SS = (long long)S * S;
    const float attn_scale = 1.0f / sqrtf((float)d);

    // 0. convert weights to fp16
    {
        long long n4;
        n4 = (long long)3 * d * d / 4; cvt_k<<<(unsigned)((n4 + 255) / 256), 256>>>(Wqkv, wqkv, n4);
        n4 = (long long)d * d / 4;     cvt_k<<<(unsigned)((n4 + 255) / 256), 256>>>(Wo,   wo,   n4);
        n4 = (long long)f * d / 4;     cvt_k<<<(unsigned)((n4 + 255) / 256), 256>>>(W1,   w1,   n4);
        n4 = (long long)d * f / 4;     cvt_k<<<(unsigned)((n4 + 255) / 256), 256>>>(W2,   w2,   n4);
    }
    // 1. LN1 (fp32 residual + half GEMM input)
    ln_k<<<M, 256>>>(src, g1, be1, xln, xln_h);
    // 2. QKV projection (half out)
    hgemm_k<<<dim3(3 * d / 128, M / 128, 1), NTHREADS, SMEM_BYTES>>>(
        xln_h, d, 0, wqkv, d, 0, qkv_h, 3 * d, 0, d, bqkv, nullptr, 1.f, 0, 0, 0, 1);
    // 3. RoPE -> half Q,K
    rope_k<<<dim3(S, B), 256>>>(qkv_h, q_h, k_h);
    // 4. V transpose -> half
    vtrans_k<<<dim3(d / 32, S / 32, B), dim3(32, 8)>>>(qkv_h, vt_h);
    // 5. scores = scale * Q K^T (fp32 out, causal block skip)
    hgemm_k<<<dim3(S / 128, S / 128, B), NTHREADS, SMEM_BYTES>>>(
        q_h, d, Sd, k_h, d, Sd, sc, S, SS, d, nullptr, nullptr, attn_scale, 0, 1, 0, 0);
    // 6. softmax -> half probs
    softmax_k<<<dim3(S, B), 256>>>(sc, p_h);
    // 7. attn = P V (K truncated; half out)
    hgemm_k<<<dim3(d / 128, S / 128, B), NTHREADS, SMEM_BYTES>>>(
        p_h, S, SS, vt_h, S, Sd, at_h, d, Sd, S, nullptr, nullptr, 1.f, 0, 0, 1, 1);
    // 8. src2 = xln + attn Wo^T + bo (fp32 out)
    hgemm_k<<<dim3(d / 128, M / 128, 1), NTHREADS, SMEM_BYTES>>>(
        at_h, d, 0, wo, d, 0, src2, d, 0, d, bo, xln, 1.f, 0, 0, 0, 0);
    // 9. LN2 -> half only
    ln_k<<<M, 256>>>(src2, g2, be2, nullptr, hln_h);
    // 10. h1 = relu(hln W1^T + b1) (half out)
    hgemm_k<<<dim3(f / 128, M / 128, 1), NTHREADS, SMEM_BYTES>>>(
        hln_h, d, 0, w1, d, 0, h1_h, f, 0, d, b1, nullptr, 1.f, 1, 0, 0, 1);
    // 11. out = src2 + h1 W2^T + b2 (fp32 out)
    hgemm_k<<<dim3(d / 128, M / 128, 1), NTHREADS, SMEM_BYTES>>>(
        h1_h, f, 0, w2, f, 0, out, d, 0, f, b2, src2, 1.f, 0, 0, 0, 0);
}